// round 16
// baseline (speedup 1.0000x reference)
#include <cuda_runtime.h>

#define N 8192
#define THREADS 256
#define TILE_ROWS 32
#define TILE_COLS 1024                 // 256 threads * 4 cols
#define ROW_TILES (N / TILE_ROWS)      // 256
#define COL_TILES (N / TILE_COLS)      // 8
#define GRID (ROW_TILES * COL_TILES)   // 2048 blocks
#define F4_PER_ROW (N / 4)             // 2048
#define LOG2E 1.44269504088896340736f
#define LN2   0.69314718055994530942f

// Packed accumulator: bits[50:64) = block count, bits[0:50) = sum * 2^19.
// One relaxed 64-bit atomicAdd per block: reduction + last-block election via
// the return value; no fences anywhere. Integer adds commute -> deterministic.
#define SUM_SCALE  524288.0f           // 2^19
#define COUNT_UNIT (1ULL << 50)
#define SUM_MASK   (COUNT_UNIT - 1ULL)

__device__ unsigned long long g_pack;  // zero at load; reset by last block each run

// softplus in log2 units: log2(1 + 2^x) = max(x,0) + log2(1 + 2^(-|x|))
__device__ __forceinline__ float softplus2(float x) {
    float e = exp2f(0.0f - fabsf(x));
    return fmaxf(x, 0.0f) + __log2f(1.0f + e);
}

__global__ void __launch_bounds__(THREADS, 8)
bt_tile_kernel(const float* __restrict__ win,
               const float* __restrict__ betas,
               float* __restrict__ out) {
    const int row0 = (blockIdx.x & (ROW_TILES - 1)) * TILE_ROWS;
    const int col0 = (blockIdx.x >> 8) * TILE_COLS;

    __shared__ float s_biL[TILE_ROWS];
    if (threadIdx.x < TILE_ROWS)
        s_biL[threadIdx.x] = __ldg(betas + row0 + threadIdx.x) * LOG2E;
    __syncthreads();

    // This thread's 4 fixed columns: betas loaded ONCE, pre-scaled to log2.
    const int j4 = (col0 >> 2) + threadIdx.x;
    float4 bj = __ldg(reinterpret_cast<const float4*>(betas) + j4);
    float xb[4];
    xb[0] = bj.x * LOG2E; xb[1] = bj.y * LOG2E;
    xb[2] = bj.z * LOG2E; xb[3] = bj.w * LOG2E;

    const float4* wp = reinterpret_cast<const float4*>(win)
                       + (size_t)row0 * F4_PER_ROW + j4;

    float acc0 = 0.0f, acc1 = 0.0f;

    // One LDG.128 + one broadcast LDS per 4 elements (was 2x LDG.128).
    #pragma unroll 4
    for (int r = 0; r < TILE_ROWS; r++) {
        float4 w = __ldcs(wp);
        wp += F4_PER_ROW;
        const float biL = s_biL[r];           // broadcast, conflict-free

        acc0 = fmaf(w.x, softplus2(xb[0] - biL), acc0);
        acc1 = fmaf(w.y, softplus2(xb[1] - biL), acc1);
        acc0 = fmaf(w.z, softplus2(xb[2] - biL), acc0);
        acc1 = fmaf(w.w, softplus2(xb[3] - biL), acc1);
    }

    float acc = acc0 + acc1;

    // Diagonal fixup: subtract (d,d) terms this tile contains, recomputed with
    // the same formula (cancellation to fp32 ulp; budget 1e-3, error ~1e-7).
    {
        const int j0 = col0 + threadIdx.x * 4;
        #pragma unroll
        for (int k = 0; k < 4; k++) {
            const int d = j0 + k;
            const int r = d - row0;
            if ((unsigned)r < TILE_ROWS) {
                float wd = __ldg(win + (size_t)d * N + d);
                acc -= wd * softplus2(xb[k] - s_biL[r]);
            }
        }
    }

    // warp reduction
    #pragma unroll
    for (int off = 16; off > 0; off >>= 1)
        acc += __shfl_xor_sync(0xFFFFFFFFu, acc, off);

    __shared__ float warp_sums[THREADS / 32];
    const int lane = threadIdx.x & 31;
    const int wid  = threadIdx.x >> 5;
    if (lane == 0) warp_sums[wid] = acc;
    __syncthreads();

    // Single relaxed 64-bit atomic: reduction + election + handoff.
    if (threadIdx.x == 0) {
        float v = warp_sums[0];
        #pragma unroll
        for (int i = 1; i < THREADS / 32; i++) v += warp_sums[i];

        // v >= 0: all products non-negative; diagonal subtraction removes
        // terms contained in this block's own sum.
        unsigned long long myfix =
            (unsigned long long)(fmaxf(v, 0.0f) * SUM_SCALE + 0.5f);
        unsigned long long old = atomicAdd(&g_pack, COUNT_UNIT + myfix);

        if ((old >> 50) == (unsigned long long)(GRID - 1)) {  // last block
            unsigned long long total = (old & SUM_MASK) + myfix;
            *out = (float)((double)total * ((double)LN2 / 524288.0));
            g_pack = 0ULL;                     // reset for next graph replay;
        }                                      // kernel-boundary orders this
    }
}

extern "C" void kernel_launch(void* const* d_in, const int* in_sizes, int n_in,
                              void* d_out, int out_size) {
    const float* win   = (const float*)d_in[0];
    const float* betas = (const float*)d_in[1];
    float* out = (float*)d_out;

    bt_tile_kernel<<<GRID, THREADS>>>(win, betas, out);   // single graph node
}

// round 17
// speedup vs baseline: 1.1058x; 1.1058x over previous
#include <cuda_runtime.h>

#define N 8192
#define THREADS 256
#define GRID (N / 2)                  // 4096 blocks, 2 rows each
#define F4_PER_ROW (N / 4)            // 2048 float4 per row
#define ITERS (F4_PER_ROW / THREADS)  // 8 float4 per thread per row
#define LOG2E 1.44269504088896340736f
#define LN2   0.69314718055994530942f

// Packed accumulator: bits[50:64) = block count, bits[0:50) = sum * 2^19.
// One relaxed 64-bit atomicAdd per block: reduction + last-block election via
// the return value; no fences anywhere. Integer adds commute -> deterministic.
#define SUM_SCALE  524288.0f          // 2^19
#define COUNT_UNIT (1ULL << 50)
#define SUM_MASK   (COUNT_UNIT - 1ULL)

__device__ unsigned long long g_pack; // zero at load; reset by last block each run

// softplus in log2 units: log2(1 + 2^x) = max(x,0) + log2(1 + 2^(-|x|))
__device__ __forceinline__ float softplus2(float x) {
    float e = exp2f(0.0f - fabsf(x));
    return fmaxf(x, 0.0f) + __log2f(1.0f + e);
}

__global__ void __launch_bounds__(THREADS, 8)
bt_rowpair_kernel(const float* __restrict__ win,
                  const float* __restrict__ betas,
                  float* __restrict__ out) {
    const int row0 = blockIdx.x << 1;         // even row
    const int row1 = row0 | 1;                // odd row

    const float bi0L = __ldg(betas + row0) * LOG2E;
    const float bi1L = __ldg(betas + row1) * LOG2E;

    const float4* w0p = reinterpret_cast<const float4*>(win) + (size_t)row0 * F4_PER_ROW;
    const float4* w1p = w0p + F4_PER_ROW;
    const float4* b4  = reinterpret_cast<const float4*>(betas);

    float accA = 0.0f, accB = 0.0f;

    #pragma unroll
    for (int k = 0; k < ITERS; k++) {
        const int p = k * THREADS + threadIdx.x;
        float4 w0 = __ldcs(w0p + p);          // row0 stream (contiguous, R6 pattern)
        float4 w1 = __ldcs(w1p + p);          // row1 stream (independent)
        float4 bj = __ldg(b4 + p);            // ONE betas load serves BOTH rows

        const float xb0 = bj.x * LOG2E;
        const float xb1 = bj.y * LOG2E;
        const float xb2 = bj.z * LOG2E;
        const float xb3 = bj.w * LOG2E;

        accA = fmaf(w0.x, softplus2(xb0 - bi0L), accA);
        accB = fmaf(w0.y, softplus2(xb1 - bi0L), accB);
        accA = fmaf(w0.z, softplus2(xb2 - bi0L), accA);
        accB = fmaf(w0.w, softplus2(xb3 - bi0L), accB);

        accA = fmaf(w1.x, softplus2(xb0 - bi1L), accA);
        accB = fmaf(w1.y, softplus2(xb1 - bi1L), accB);
        accA = fmaf(w1.z, softplus2(xb2 - bi1L), accA);
        accB = fmaf(w1.w, softplus2(xb3 - bi1L), accB);
    }

    float acc = accA + accB;

    // Remove both diagonal terms, recomputed with identical FP ops so the
    // cancellation against the main-loop contribution is exact.
    if (threadIdx.x == 0) {
        float wd0 = __ldg(win + (size_t)row0 * N + row0);
        float wd1 = __ldg(win + (size_t)row1 * N + row1);
        acc -= wd0 * softplus2(__ldg(betas + row0) * LOG2E - bi0L);
        acc -= wd1 * softplus2(__ldg(betas + row1) * LOG2E - bi1L);
    }

    // warp reduction
    #pragma unroll
    for (int off = 16; off > 0; off >>= 1)
        acc += __shfl_xor_sync(0xFFFFFFFFu, acc, off);

    __shared__ float warp_sums[THREADS / 32];
    const int lane = threadIdx.x & 31;
    const int wid  = threadIdx.x >> 5;
    if (lane == 0) warp_sums[wid] = acc;
    __syncthreads();

    // Single relaxed 64-bit atomic: reduction + election + handoff in one op.
    if (threadIdx.x == 0) {
        float v = warp_sums[0];
        #pragma unroll
        for (int i = 1; i < THREADS / 32; i++) v += warp_sums[i];

        // v >= 0: all products non-negative; diagonal subtraction removes
        // terms contained in this block's own sum.
        unsigned long long myfix =
            (unsigned long long)(fmaxf(v, 0.0f) * SUM_SCALE + 0.5f);
        unsigned long long old = atomicAdd(&g_pack, COUNT_UNIT + myfix);

        if ((old >> 50) == (unsigned long long)(GRID - 1)) {  // last block
            unsigned long long total = (old & SUM_MASK) + myfix;
            *out = (float)((double)total * ((double)LN2 / 524288.0));
            g_pack = 0ULL;                    // reset for next graph replay;
        }                                     // kernel-boundary orders this store
    }
}

extern "C" void kernel_launch(void* const* d_in, const int* in_sizes, int n_in,
                              void* d_out, int out_size) {
    const float* win   = (const float*)d_in[0];
    const float* betas = (const float*)d_in[1];
    float* out = (float*)d_out;

    bt_rowpair_kernel<<<GRID, THREADS>>>(win, betas, out);   // single graph node
}